// round 1
// baseline (speedup 1.0000x reference)
#include <cuda_runtime.h>
#include <cstdint>

#define M_TOTAL 32768
#define K_DIM   256
#define NCODES  8192
#define MT      128
#define NT      32
#define NSPLIT  4
#define STRIPE  (NCODES/NSPLIT)   // 2048
#define NTILES  (STRIPE/NT)       // 64
#define THREADS 256
#define SMEM_BYTES ((K_DIM*MT + 2*K_DIM*NT)*4)   // 131072 + 65536 = 196608

__device__ float g_hesq[NCODES];
__device__ float g_embT[NCODES*K_DIM];
__device__ unsigned long long g_packed[M_TOTAL];

// ---------------------------------------------------------------------------
// Prep: half |e_k|^2 per code + reset packed argmin array
// ---------------------------------------------------------------------------
__global__ void prep_kernel(const float* __restrict__ embed) {
    int n = blockIdx.x * blockDim.x + threadIdx.x;
    if (n < NCODES) {
        float s = 0.f;
        #pragma unroll 8
        for (int k = 0; k < K_DIM; k++) {
            float v = embed[k * NCODES + n];
            s += v * v;
        }
        g_hesq[n] = 0.5f * s;
    }
    for (int i = n; i < M_TOTAL; i += gridDim.x * blockDim.x)
        g_packed[i] = 0xFFFFFFFFFFFFFFFFULL;
}

// ---------------------------------------------------------------------------
// Transpose codebook [K_DIM, NCODES] -> [NCODES, K_DIM] for coalesced gather
// ---------------------------------------------------------------------------
__global__ void transpose_kernel(const float* __restrict__ embed) {
    __shared__ float tile[32][33];
    int bx = blockIdx.x, by = blockIdx.y;
    int tx = threadIdx.x, ty = threadIdx.y;
    tile[ty][tx] = embed[(by * 32 + ty) * NCODES + bx * 32 + tx];
    __syncthreads();
    g_embT[(bx * 32 + ty) * K_DIM + by * 32 + tx] = tile[tx][ty];
}

// ---------------------------------------------------------------------------
// Fused GEMM + argmin
// ---------------------------------------------------------------------------
__device__ __forceinline__ unsigned enc_f(float f) {
    unsigned u = __float_as_uint(f);
    return (u & 0x80000000u) ? ~u : (u | 0x80000000u);
}

__device__ __forceinline__ void cpa16(float* dst, const float* src) {
    unsigned s = (unsigned)__cvta_generic_to_shared(dst);
    asm volatile("cp.async.cg.shared.global [%0], [%1], 16;" :: "r"(s), "l"(src));
}

extern __shared__ float smem[];

__global__ __launch_bounds__(THREADS, 1)
void score_kernel(const float* __restrict__ x, const float* __restrict__ embed) {
    float* xs = smem;               // [K_DIM][MT] transposed x tile
    float* es = smem + K_DIM * MT;  // [2][K_DIM][NT] double-buffered code tiles

    const int tid = threadIdx.x;
    const int tx = tid & 15;        // col group (2 cols)
    const int ty = tid >> 4;        // row group (8 rows)
    const int r0 = blockIdx.x * MT;
    const int nstart = blockIdx.y * STRIPE;

    // Load x tile transposed: xs[k][m]
    const float4* x4 = reinterpret_cast<const float4*>(x + (size_t)r0 * K_DIM);
    for (int i = tid; i < MT * (K_DIM / 4); i += THREADS) {
        int m = i >> 6;             // K_DIM/4 = 64 float4 per row
        int kc = i & 63;
        float4 v = x4[m * 64 + kc];
        xs[(4 * kc + 0) * MT + m] = v.x;
        xs[(4 * kc + 1) * MT + m] = v.y;
        xs[(4 * kc + 2) * MT + m] = v.z;
        xs[(4 * kc + 3) * MT + m] = v.w;
    }

    // Prefetch code tile 0
    {
        const float* src = embed + nstart;
        for (int i = tid; i < K_DIM * (NT / 4); i += THREADS) {
            int k = i >> 3;         // NT/4 = 8 float4 per k-row
            int nc = i & 7;
            cpa16(es + k * NT + 4 * nc, src + k * NCODES + 4 * nc);
        }
        asm volatile("cp.async.commit_group;");
    }

    float best[8];
    unsigned bidx[8];
    #pragma unroll
    for (int j = 0; j < 8; j++) { best[j] = 3.4e38f; bidx[j] = 0; }

    for (int t = 0; t < NTILES; t++) {
        const int buf = t & 1;
        if (t + 1 < NTILES) {
            const float* src = embed + nstart + (t + 1) * NT;
            float* dst = es + (buf ^ 1) * K_DIM * NT;
            for (int i = tid; i < K_DIM * (NT / 4); i += THREADS) {
                int k = i >> 3;
                int nc = i & 7;
                cpa16(dst + k * NT + 4 * nc, src + k * NCODES + 4 * nc);
            }
            asm volatile("cp.async.commit_group;");
            asm volatile("cp.async.wait_group 1;");
        } else {
            asm volatile("cp.async.wait_group 0;");
        }
        __syncthreads();

        const int nbase = nstart + t * NT + tx * 2;
        const float h0 = __ldg(&g_hesq[nbase]);
        const float h1 = __ldg(&g_hesq[nbase + 1]);

        float acc[8][2];
        #pragma unroll
        for (int j = 0; j < 8; j++) { acc[j][0] = 0.f; acc[j][1] = 0.f; }

        const float* esb = es + buf * K_DIM * NT;
        #pragma unroll 8
        for (int k = 0; k < K_DIM; k++) {
            const float4* ap = reinterpret_cast<const float4*>(xs + k * MT + ty * 8);
            float4 a0 = ap[0];
            float4 a1 = ap[1];
            float2 b = *reinterpret_cast<const float2*>(esb + k * NT + tx * 2);
            acc[0][0] += a0.x * b.x;  acc[0][1] += a0.x * b.y;
            acc[1][0] += a0.y * b.x;  acc[1][1] += a0.y * b.y;
            acc[2][0] += a0.z * b.x;  acc[2][1] += a0.z * b.y;
            acc[3][0] += a0.w * b.x;  acc[3][1] += a0.w * b.y;
            acc[4][0] += a1.x * b.x;  acc[4][1] += a1.x * b.y;
            acc[5][0] += a1.y * b.x;  acc[5][1] += a1.y * b.y;
            acc[6][0] += a1.z * b.x;  acc[6][1] += a1.z * b.y;
            acc[7][0] += a1.w * b.x;  acc[7][1] += a1.w * b.y;
        }

        #pragma unroll
        for (int j = 0; j < 8; j++) {
            float s0 = h0 - acc[j][0];
            float s1 = h1 - acc[j][1];
            if (s0 < best[j]) { best[j] = s0; bidx[j] = (unsigned)nbase; }
            if (s1 < best[j]) { best[j] = s1; bidx[j] = (unsigned)(nbase + 1); }
        }
        __syncthreads();
    }

    // Reduce across the 16 col-group lanes (same warp, width 16)
    #pragma unroll
    for (int j = 0; j < 8; j++) {
        float v = best[j];
        unsigned bi = bidx[j];
        #pragma unroll
        for (int off = 8; off > 0; off >>= 1) {
            float ov = __shfl_down_sync(0xffffffffu, v, off, 16);
            unsigned oi = __shfl_down_sync(0xffffffffu, bi, off, 16);
            if (ov < v || (ov == v && oi < bi)) { v = ov; bi = oi; }
        }
        if (tx == 0) {
            unsigned long long p = ((unsigned long long)enc_f(v) << 32) | (unsigned long long)bi;
            atomicMin(&g_packed[r0 + ty * 8 + j], p);
        }
    }
}

// ---------------------------------------------------------------------------
// Gather winning code rows (coalesced via transposed codebook)
// ---------------------------------------------------------------------------
__global__ void gather_kernel(float* __restrict__ out) {
    int r = blockIdx.x * 4 + (threadIdx.x >> 6);
    int c = threadIdx.x & 63;
    unsigned idx = (unsigned)(g_packed[r] & 0xFFFFFFFFULL);
    idx &= (NCODES - 1);  // safety mask, no-op when correct
    const float4* src = reinterpret_cast<const float4*>(g_embT + (size_t)idx * K_DIM);
    reinterpret_cast<float4*>(out + (size_t)r * K_DIM)[c] = src[c];
}

// ---------------------------------------------------------------------------
extern "C" void kernel_launch(void* const* d_in, const int* in_sizes, int n_in,
                              void* d_out, int out_size) {
    const float* x = (const float*)d_in[0];      // [32768, 256]
    const float* embed = (const float*)d_in[1];  // [256, 8192]
    float* out = (float*)d_out;                  // [32768, 256]

    cudaFuncSetAttribute(score_kernel, cudaFuncAttributeMaxDynamicSharedMemorySize,
                         SMEM_BYTES);

    prep_kernel<<<NCODES / 256, 256>>>(embed);
    transpose_kernel<<<dim3(NCODES / 32, K_DIM / 32), dim3(32, 32)>>>(embed);
    score_kernel<<<dim3(M_TOTAL / MT, NSPLIT), THREADS, SMEM_BYTES>>>(x, embed);
    gather_kernel<<<M_TOTAL / 4, 256>>>(out);
}

// round 6
// speedup vs baseline: 1.9795x; 1.9795x over previous
#include <cuda_runtime.h>
#include <cuda_bf16.h>
#include <cstdint>

#define M_TOTAL 32768
#define K_DIM   256
#define NCODES  8192
#define MT      128
#define NSPLIT  4
#define STRIPE  2048
#define NT      128
#define NTILES  16            // per stripe
#define CHUNKS  128           // 16 tiles * 8 chunks (4 hi + 4 lo)
#define THREADS 256
#define TAU     0.05f

// SMEM layout (bytes)
#define A_STRIDE_B  528       // 264 bf16 (256 + 8 pad)
#define B_STRIDE_B  144       // 72 bf16 (64 + 8 pad)
#define SM_AHI      0         // 128*528 = 67584
#define SM_ALO      67584     // 67584
#define SM_B        135168    // 4 stages * 18432 = 73728
#define B_STAGE_B   18432
#define SM_HESQ     208896    // 2048 floats = 8192
#define SM_MERGE    135168    // reuse B ring after main loop (32768 B)
#define SMEM_TOTAL  217088

// device globals
__device__ float          g_hesq[NCODES];
__device__ float          g_embT[(size_t)NCODES * K_DIM];
__device__ __nv_bfloat16  g_ebf_hi[(size_t)NCODES * K_DIM];
__device__ __nv_bfloat16  g_ebf_lo[(size_t)NCODES * K_DIM];
__device__ __nv_bfloat16  g_xhi[(size_t)M_TOTAL * K_DIM];
__device__ __nv_bfloat16  g_xlo[(size_t)M_TOTAL * K_DIM];
__device__ float4         g_pvals[NSPLIT][M_TOTAL];
__device__ uint4          g_pidx[NSPLIT][M_TOTAL];
__device__ unsigned       g_idx[M_TOTAL];
__device__ int            g_nflag;
__device__ int            g_flag[M_TOTAL];

// ---- helpers -------------------------------------------------------------
__device__ __forceinline__ uint32_t smem_u32(const void* p) {
    uint32_t a;
    asm("{ .reg .u64 t; cvta.to.shared.u64 t, %1; cvt.u32.u64 %0, t; }" : "=r"(a) : "l"(p));
    return a;
}
__device__ __forceinline__ void cpa16(uint32_t dst, const void* src) {
    asm volatile("cp.async.cg.shared.global [%0], [%1], 16;" :: "r"(dst), "l"(src));
}
#define CP_COMMIT() asm volatile("cp.async.commit_group;" ::: "memory")
#define CP_WAIT2()  asm volatile("cp.async.wait_group 2;" ::: "memory")

__device__ __forceinline__ void ldm4(uint32_t* r, uint32_t addr) {
    asm volatile("ldmatrix.sync.aligned.m8n8.x4.shared.b16 {%0,%1,%2,%3}, [%4];"
                 : "=r"(r[0]), "=r"(r[1]), "=r"(r[2]), "=r"(r[3]) : "r"(addr));
}
__device__ __forceinline__ void mma_bf16(float* d, const uint32_t* a, uint32_t b0, uint32_t b1) {
    asm volatile("mma.sync.aligned.m16n8k16.row.col.f32.bf16.bf16.f32 "
                 "{%0,%1,%2,%3},{%4,%5,%6,%7},{%8,%9},{%0,%1,%2,%3};"
                 : "+f"(d[0]), "+f"(d[1]), "+f"(d[2]), "+f"(d[3])
                 : "r"(a[0]), "r"(a[1]), "r"(a[2]), "r"(a[3]), "r"(b0), "r"(b1));
}

// ---------------------------------------------------------------------------
// prep kernels
// ---------------------------------------------------------------------------
__global__ void prep_kernel(const float* __restrict__ embed) {
    int n = blockIdx.x * blockDim.x + threadIdx.x;
    if (n == 0) g_nflag = 0;
    if (n < NCODES) {
        float s = 0.f;
        #pragma unroll 8
        for (int k = 0; k < K_DIM; k++) {
            float v = embed[(size_t)k * NCODES + n];
            s += v * v;
        }
        g_hesq[n] = 0.5f * s;
    }
}

__global__ void transpose_split_kernel(const float* __restrict__ embed) {
    __shared__ float tile[32][33];
    int bx = blockIdx.x, by = blockIdx.y;
    int tx = threadIdx.x, ty = threadIdx.y;
    tile[ty][tx] = embed[(size_t)(by * 32 + ty) * NCODES + bx * 32 + tx];
    __syncthreads();
    float v = tile[tx][ty];
    int n = bx * 32 + ty, k = by * 32 + tx;
    size_t o = (size_t)n * K_DIM + k;
    g_embT[o] = v;
    __nv_bfloat16 h = __float2bfloat16_rn(v);
    g_ebf_hi[o] = h;
    g_ebf_lo[o] = __float2bfloat16_rn(v - __bfloat162float(h));
}

__global__ void xsplit_kernel(const float* __restrict__ x) {
    int i = blockIdx.x * blockDim.x + threadIdx.x;   // float4 index
    float4 v = reinterpret_cast<const float4*>(x)[i];
    __nv_bfloat16 h0 = __float2bfloat16_rn(v.x), h1 = __float2bfloat16_rn(v.y);
    __nv_bfloat16 h2 = __float2bfloat16_rn(v.z), h3 = __float2bfloat16_rn(v.w);
    unsigned hw0 = (unsigned)__bfloat16_as_ushort(h0) | ((unsigned)__bfloat16_as_ushort(h1) << 16);
    unsigned hw1 = (unsigned)__bfloat16_as_ushort(h2) | ((unsigned)__bfloat16_as_ushort(h3) << 16);
    __nv_bfloat16 l0 = __float2bfloat16_rn(v.x - __bfloat162float(h0));
    __nv_bfloat16 l1 = __float2bfloat16_rn(v.y - __bfloat162float(h1));
    __nv_bfloat16 l2 = __float2bfloat16_rn(v.z - __bfloat162float(h2));
    __nv_bfloat16 l3 = __float2bfloat16_rn(v.w - __bfloat162float(h3));
    unsigned lw0 = (unsigned)__bfloat16_as_ushort(l0) | ((unsigned)__bfloat16_as_ushort(l1) << 16);
    unsigned lw1 = (unsigned)__bfloat16_as_ushort(l2) | ((unsigned)__bfloat16_as_ushort(l3) << 16);
    reinterpret_cast<uint2*>(g_xhi)[i] = make_uint2(hw0, hw1);
    reinterpret_cast<uint2*>(g_xlo)[i] = make_uint2(lw0, lw1);
}

// ---------------------------------------------------------------------------
// fused bf16x3 HMMA GEMM + per-stripe top-4
// ---------------------------------------------------------------------------
extern __shared__ char smc[];

__device__ __forceinline__ void issue_chunk(uint32_t smem, int c, int tid, int nstart) {
    int t = c >> 3, sub = c & 7;
    int kc = sub & 3;
    const char* base = (const char*)((sub < 4) ? g_ebf_hi : g_ebf_lo)
                     + ((size_t)(nstart + t * NT) * K_DIM + kc * 64) * 2;
    uint32_t dst = smem + SM_B + (uint32_t)(c & 3) * B_STAGE_B;
    #pragma unroll
    for (int j = 0; j < 4; j++) {
        int i = tid + j * THREADS;          // 0..1023
        int n = i >> 3, ch = i & 7;
        cpa16(dst + n * B_STRIDE_B + ch * 16, base + (size_t)n * 512 + ch * 16);
    }
}

__global__ void __launch_bounds__(THREADS, 1)
score_kernel() {
    const int tid = threadIdx.x;
    const int lane = tid & 31;
    const int warp = tid >> 5;
    const int mwarp = warp >> 1;            // 0..3
    const int nwarp = warp & 1;             // 0..1
    const int r0 = blockIdx.x * MT;
    const int nstart = blockIdx.y * STRIPE;
    const uint32_t smem = smem_u32(smc);

    // ---- prologue: A (hi+lo) + hesq stripe, then 2 B chunks ----
    {
        const char* xh = (const char*)g_xhi + (size_t)r0 * 512;
        const char* xl = (const char*)g_xlo + (size_t)r0 * 512;
        for (int i = tid; i < 128 * 32; i += THREADS) {
            int row = i >> 5, ch = i & 31;
            cpa16(smem + SM_AHI + row * A_STRIDE_B + ch * 16, xh + (size_t)row * 512 + ch * 16);
            cpa16(smem + SM_ALO + row * A_STRIDE_B + ch * 16, xl + (size_t)row * 512 + ch * 16);
        }
        for (int i = tid; i < 512; i += THREADS)
            cpa16(smem + SM_HESQ + i * 16, g_hesq + nstart + i * 4);
        CP_COMMIT();
        issue_chunk(smem, 0, tid, nstart); CP_COMMIT();
        issue_chunk(smem, 1, tid, nstart); CP_COMMIT();
    }

    float acc[2][8][4];
    float tv[4][4];
    unsigned ti[4][4];
    #pragma unroll
    for (int r = 0; r < 4; r++)
        #pragma unroll
        for (int j = 0; j < 4; j++) { tv[r][j] = 3.4e38f; ti[r][j] = 0; }

    const uint32_t a_lane = (uint32_t)((lane & 15) * A_STRIDE_B + (lane >> 4) * 16);
    const uint32_t b_lane = (uint32_t)((lane & 15) * B_STRIDE_B + (lane >> 4) * 16);
    const uint32_t aHi = smem + SM_AHI + mwarp * 32 * A_STRIDE_B + a_lane;
    const uint32_t aLo = aHi + (SM_ALO - SM_AHI);
    const float* hesq_s = (const float*)(smc + SM_HESQ);

    for (int c = 0; c < CHUNKS; c++) {
        if (c + 2 < CHUNKS) issue_chunk(smem, c + 2, tid, nstart);
        CP_COMMIT();
        CP_WAIT2();
        __syncthreads();

        const int sub = c & 7;
        const int hi = (sub < 4);
        const int kc = sub & 3;
        const uint32_t kbyte = (uint32_t)kc * 128;
        const uint32_t Bb = smem + SM_B + (uint32_t)(c & 3) * B_STAGE_B
                          + (uint32_t)(nwarp * 64) * B_STRIDE_B + b_lane;

        if (sub == 0) {                     // new tile: clear accumulators
            #pragma unroll
            for (int ms = 0; ms < 2; ms++)
                #pragma unroll
                for (int ns = 0; ns < 8; ns++)
                    #pragma unroll
                    for (int j = 0; j < 4; j++) acc[ms][ns][j] = 0.f;
        }

        #pragma unroll
        for (int ks = 0; ks < 4; ks++) {
            const uint32_t koff = kbyte + ks * 32;
            uint32_t bf[4][4];
            #pragma unroll
            for (int g = 0; g < 4; g++) ldm4(bf[g], Bb + ks * 32 + g * (16 * B_STRIDE_B));
            uint32_t ah0[4], ah1[4];
            ldm4(ah0, aHi + koff);
            ldm4(ah1, aHi + 16 * A_STRIDE_B + koff);
            if (hi) {
                uint32_t al0[4], al1[4];
                ldm4(al0, aLo + koff);
                ldm4(al1, aLo + 16 * A_STRIDE_B + koff);
                #pragma unroll
                for (int ns = 0; ns < 8; ns++) {
                    uint32_t b0 = bf[ns >> 1][ns & 1], b1 = bf[ns >> 1][(ns & 1) + 2];
                    mma_bf16(acc[0][ns], ah0, b0, b1);
                    mma_bf16(acc[1][ns], ah1, b0, b1);
                    mma_bf16(acc[0][ns], al0, b0, b1);
                    mma_bf16(acc[1][ns], al1, b0, b1);
                }
            } else {
                #pragma unroll
                for (int ns = 0; ns < 8; ns++) {
                    uint32_t b0 = bf[ns >> 1][ns & 1], b1 = bf[ns >> 1][(ns & 1) + 2];
                    mma_bf16(acc[0][ns], ah0, b0, b1);
                    mma_bf16(acc[1][ns], ah1, b0, b1);
                }
            }
        }

        if (sub == 7) {                     // tile done: score + top-4
            const int t = c >> 3;
            const int colbase = t * NT + nwarp * 64 + (lane & 3) * 2;
            #pragma unroll
            for (int ms = 0; ms < 2; ms++)
                #pragma unroll
                for (int ns = 0; ns < 8; ns++)
                    #pragma unroll
                    for (int i = 0; i < 4; i++) {
                        int col = colbase + ns * 8 + (i & 1);
                        float s = hesq_s[col] - acc[ms][ns][i];
                        const int rid = ms * 2 + (i >> 1);
                        if (s < tv[rid][3]) {
                            unsigned n = (unsigned)(nstart + col);
                            if (s < tv[rid][0]) {
                                tv[rid][3]=tv[rid][2]; ti[rid][3]=ti[rid][2];
                                tv[rid][2]=tv[rid][1]; ti[rid][2]=ti[rid][1];
                                tv[rid][1]=tv[rid][0]; ti[rid][1]=ti[rid][0];
                                tv[rid][0]=s; ti[rid][0]=n;
                            } else if (s < tv[rid][1]) {
                                tv[rid][3]=tv[rid][2]; ti[rid][3]=ti[rid][2];
                                tv[rid][2]=tv[rid][1]; ti[rid][2]=ti[rid][1];
                                tv[rid][1]=s; ti[rid][1]=n;
                            } else if (s < tv[rid][2]) {
                                tv[rid][3]=tv[rid][2]; ti[rid][3]=ti[rid][2];
                                tv[rid][2]=s; ti[rid][2]=n;
                            } else { tv[rid][3]=s; ti[rid][3]=n; }
                        }
                    }
        }
        __syncthreads();
    }

    // ---- per-CTA merge: 8 partial top-4 lists per row -> stripe top-4 ----
    char* scr = smc + SM_MERGE;
    const int slot = nwarp * 4 + (lane & 3);
    #pragma unroll
    for (int rid = 0; rid < 4; rid++) {
        int row = mwarp * 32 + (rid >> 1) * 16 + (rid & 1) * 8 + (lane >> 2);
        char* p = scr + (row * 8 + slot) * 32;
        *reinterpret_cast<float4*>(p)      = make_float4(tv[rid][0], tv[rid][1], tv[rid][2], tv[rid][3]);
        *reinterpret_cast<uint4*>(p + 16)  = make_uint4(ti[rid][0], ti[rid][1], ti[rid][2], ti[rid][3]);
    }
    __syncthreads();

    if (tid < MT) {
        float v[4] = {3.4e38f, 3.4e38f, 3.4e38f, 3.4e38f};
        unsigned id[4] = {0, 0, 0, 0};
        const char* p = scr + tid * 8 * 32;
        for (int s = 0; s < 8; s++) {
            float4 pv = *reinterpret_cast<const float4*>(p + s * 32);
            uint4  pi = *reinterpret_cast<const uint4*>(p + s * 32 + 16);
            float cv[4] = {pv.x, pv.y, pv.z, pv.w};
            unsigned ci[4] = {pi.x, pi.y, pi.z, pi.w};
            #pragma unroll
            for (int j = 0; j < 4; j++) {
                float s1 = cv[j]; unsigned n1 = ci[j];
                if (s1 < v[3] || (s1 == v[3] && n1 < id[3])) {
                    if (s1 < v[0] || (s1 == v[0] && n1 < id[0])) {
                        v[3]=v[2];id[3]=id[2]; v[2]=v[1];id[2]=id[1]; v[1]=v[0];id[1]=id[0]; v[0]=s1;id[0]=n1;
                    } else if (s1 < v[1] || (s1 == v[1] && n1 < id[1])) {
                        v[3]=v[2];id[3]=id[2]; v[2]=v[1];id[2]=id[1]; v[1]=s1;id[1]=n1;
                    } else if (s1 < v[2] || (s1 == v[2] && n1 < id[2])) {
                        v[3]=v[2];id[3]=id[2]; v[2]=s1;id[2]=n1;
                    } else { v[3]=s1; id[3]=n1; }
                }
            }
        }
        g_pvals[blockIdx.y][r0 + tid] = make_float4(v[0], v[1], v[2], v[3]);
        g_pidx[blockIdx.y][r0 + tid]  = make_uint4(id[0], id[1], id[2], id[3]);
    }
}

// ---------------------------------------------------------------------------
// merge stripes + certify + exact candidate rescore
// ---------------------------------------------------------------------------
__global__ void merge_kernel(const float* __restrict__ x) {
    int r = blockIdx.x * blockDim.x + threadIdx.x;
    float v[4] = {3.4e38f, 3.4e38f, 3.4e38f, 3.4e38f};
    unsigned id[4] = {0, 0, 0, 0};
    float L = 3.4e38f;
    float allv[16]; unsigned alli[16];
    #pragma unroll
    for (int s = 0; s < NSPLIT; s++) {
        float4 pv = g_pvals[s][r];
        uint4  pi = g_pidx[s][r];
        if (pv.w < L) L = pv.w;
        float cv[4] = {pv.x, pv.y, pv.z, pv.w};
        unsigned ci[4] = {pi.x, pi.y, pi.z, pi.w};
        #pragma unroll
        for (int j = 0; j < 4; j++) {
            allv[s * 4 + j] = cv[j]; alli[s * 4 + j] = ci[j];
            float s1 = cv[j]; unsigned n1 = ci[j];
            if (s1 < v[3] || (s1 == v[3] && n1 < id[3])) {
                if (s1 < v[0] || (s1 == v[0] && n1 < id[0])) {
                    v[3]=v[2];id[3]=id[2]; v[2]=v[1];id[2]=id[1]; v[1]=v[0];id[1]=id[0]; v[0]=s1;id[0]=n1;
                } else if (s1 < v[1] || (s1 == v[1] && n1 < id[1])) {
                    v[3]=v[2];id[3]=id[2]; v[2]=v[1];id[2]=id[1]; v[1]=s1;id[1]=n1;
                } else if (s1 < v[2] || (s1 == v[2] && n1 < id[2])) {
                    v[3]=v[2];id[3]=id[2]; v[2]=s1;id[2]=n1;
                } else { v[3]=s1; id[3]=n1; }
            }
        }
    }
    if (v[1] - v[0] >= TAU) { g_idx[r] = id[0]; return; }

    // exact fp32 rescore of all 16 candidates
    const float4* xv = reinterpret_cast<const float4*>(x + (size_t)r * K_DIM);
    float best = 3.4e38f; unsigned bi = 0xFFFFFFFFu;
    for (int j = 0; j < 16; j++) {
        unsigned n = alli[j];
        const float4* er = reinterpret_cast<const float4*>(g_embT + (size_t)n * K_DIM);
        float dot = 0.f;
        #pragma unroll 8
        for (int k = 0; k < K_DIM / 4; k++) {
            float4 a = xv[k], b = er[k];
            dot += a.x * b.x + a.y * b.y + a.z * b.z + a.w * b.w;
        }
        float s = g_hesq[n] - dot;
        if (s < best || (s == best && n < bi)) { best = s; bi = n; }
    }
    g_idx[r] = bi;
    if (L - v[0] < TAU) {              // candidate set not certified complete
        int p = atomicAdd(&g_nflag, 1);
        g_flag[p] = r;
    }
}

// ---------------------------------------------------------------------------
// full exact argmin for rare uncertified rows
// ---------------------------------------------------------------------------
__global__ void fixup_full_kernel(const float* __restrict__ x) {
    __shared__ float xs[K_DIM];
    __shared__ float wv[8];
    __shared__ unsigned wi[8];
    int nf = g_nflag;
    for (int f = blockIdx.x; f < nf; f += gridDim.x) {
        int r = g_flag[f];
        for (int k = threadIdx.x; k < K_DIM; k += blockDim.x) xs[k] = x[(size_t)r * K_DIM + k];
        __syncthreads();
        float best = 3.4e38f; unsigned bi = 0xFFFFFFFFu;
        for (int n = threadIdx.x; n < NCODES; n += blockDim.x) {
            const float4* er = reinterpret_cast<const float4*>(g_embT + (size_t)n * K_DIM);
            float dot = 0.f;
            #pragma unroll 8
            for (int k = 0; k < K_DIM / 4; k++) {
                float4 b = er[k];
                dot += xs[4*k] * b.x + xs[4*k+1] * b.y + xs[4*k+2] * b.z + xs[4*k+3] * b.w;
            }
            float s = g_hesq[n] - dot;
            if (s < best || (s == best && n < bi)) { best = s; bi = n; }
        }
        #pragma unroll
        for (int off = 16; off > 0; off >>= 1) {
            float ov = __shfl_down_sync(0xffffffffu, best, off);
            unsigned oi = __shfl_down_sync(0xffffffffu, bi, off);
            if (ov < best || (ov == best && oi < bi)) { best = ov; bi = oi; }
        }
        if ((threadIdx.x & 31) == 0) { wv[threadIdx.x >> 5] = best; wi[threadIdx.x >> 5] = bi; }
        __syncthreads();
        if (threadIdx.x == 0) {
            for (int w = 1; w < 8; w++)
                if (wv[w] < best || (wv[w] == best && wi[w] < bi)) { best = wv[w]; bi = wi[w]; }
            g_idx[r] = bi;
        }
        __syncthreads();
    }
}

// ---------------------------------------------------------------------------
__global__ void gather_kernel(float* __restrict__ out) {
    int r = blockIdx.x * 4 + (threadIdx.x >> 6);
    int c = threadIdx.x & 63;
    unsigned idx = g_idx[r] & (NCODES - 1);
    const float4* src = reinterpret_cast<const float4*>(g_embT + (size_t)idx * K_DIM);
    reinterpret_cast<float4*>(out + (size_t)r * K_DIM)[c] = src[c];
}

// ---------------------------------------------------------------------------
extern "C" void kernel_launch(void* const* d_in, const int* in_sizes, int n_in,
                              void* d_out, int out_size) {
    const float* x = (const float*)d_in[0];      // [32768, 256]
    const float* embed = (const float*)d_in[1];  // [256, 8192]
    float* out = (float*)d_out;

    cudaFuncSetAttribute(score_kernel, cudaFuncAttributeMaxDynamicSharedMemorySize,
                         SMEM_TOTAL);

    prep_kernel<<<NCODES / 256, 256>>>(embed);
    transpose_split_kernel<<<dim3(NCODES / 32, K_DIM / 32), dim3(32, 32)>>>(embed);
    xsplit_kernel<<<(M_TOTAL * K_DIM / 4) / 256, 256>>>(x);
    score_kernel<<<dim3(M_TOTAL / MT, NSPLIT), THREADS, SMEM_TOTAL>>>();
    merge_kernel<<<M_TOTAL / 256, 256>>>(x);
    fixup_full_kernel<<<32, 256>>>(x);
    gather_kernel<<<M_TOTAL / 4, 256>>>(out);
}

// round 8
// speedup vs baseline: 2.0880x; 1.0548x over previous
#include <cuda_runtime.h>
#include <cuda_bf16.h>
#include <cstdint>

#define M_TOTAL 32768
#define K_DIM   256
#define NCODES  8192
#define MT      128
#define NSPLIT  4
#define STRIPE  2048
#define NT      128
#define NTILES  16            // per stripe
#define CHUNKS  128           // 16 tiles * 8 chunks (4 hi + 4 lo)
#define THREADS 512
#define TAU     0.05f

// SMEM layout (bytes)
#define A_STRIDE_B  528       // 264 bf16 (256 + 8 pad)
#define B_STRIDE_B  144       // 72 bf16 (64 + 8 pad)
#define SM_AHI      0         // 128*528 = 67584
#define SM_ALO      67584     // 67584
#define SM_B        135168    // 4 stages * 18432 = 73728
#define B_STAGE_B   18432
#define SM_HESQ     208896    // 2048 floats = 8192
#define SM_MERGE    135168    // reuse B ring after main loop (128*16*32 = 65536)
#define SMEM_TOTAL  217088

// device globals
__device__ float          g_hesq[NCODES];
__device__ float          g_embT[(size_t)NCODES * K_DIM];
__device__ __nv_bfloat16  g_ebf_hi[(size_t)NCODES * K_DIM];
__device__ __nv_bfloat16  g_ebf_lo[(size_t)NCODES * K_DIM];
__device__ __nv_bfloat16  g_xhi[(size_t)M_TOTAL * K_DIM];
__device__ __nv_bfloat16  g_xlo[(size_t)M_TOTAL * K_DIM];
__device__ float4         g_pvals[NSPLIT][M_TOTAL];
__device__ uint4          g_pidx[NSPLIT][M_TOTAL];
__device__ unsigned       g_idx[M_TOTAL];
__device__ int            g_nflag;
__device__ int            g_flag[M_TOTAL];

// ---- helpers -------------------------------------------------------------
__device__ __forceinline__ uint32_t smem_u32(const void* p) {
    uint32_t a;
    asm("{ .reg .u64 t; cvta.to.shared.u64 t, %1; cvt.u32.u64 %0, t; }" : "=r"(a) : "l"(p));
    return a;
}
__device__ __forceinline__ void cpa16(uint32_t dst, const void* src) {
    asm volatile("cp.async.cg.shared.global [%0], [%1], 16;" :: "r"(dst), "l"(src));
}
#define CP_COMMIT() asm volatile("cp.async.commit_group;" ::: "memory")
#define CP_WAIT2()  asm volatile("cp.async.wait_group 2;" ::: "memory")

__device__ __forceinline__ void ldm4(uint32_t* r, uint32_t addr) {
    asm volatile("ldmatrix.sync.aligned.m8n8.x4.shared.b16 {%0,%1,%2,%3}, [%4];"
                 : "=r"(r[0]), "=r"(r[1]), "=r"(r[2]), "=r"(r[3]) : "r"(addr));
}
__device__ __forceinline__ void mma_bf16(float* d, const uint32_t* a, uint32_t b0, uint32_t b1) {
    asm volatile("mma.sync.aligned.m16n8k16.row.col.f32.bf16.bf16.f32 "
                 "{%0,%1,%2,%3},{%4,%5,%6,%7},{%8,%9},{%0,%1,%2,%3};"
                 : "+f"(d[0]), "+f"(d[1]), "+f"(d[2]), "+f"(d[3])
                 : "r"(a[0]), "r"(a[1]), "r"(a[2]), "r"(a[3]), "r"(b0), "r"(b1));
}

// ---------------------------------------------------------------------------
// prep kernels
// ---------------------------------------------------------------------------
__global__ void prep_kernel(const float* __restrict__ embed) {
    int n = blockIdx.x * blockDim.x + threadIdx.x;
    if (n == 0) g_nflag = 0;
    if (n < NCODES) {
        float s = 0.f;
        #pragma unroll 8
        for (int k = 0; k < K_DIM; k++) {
            float v = embed[(size_t)k * NCODES + n];
            s += v * v;
        }
        g_hesq[n] = 0.5f * s;
    }
}

__global__ void transpose_split_kernel(const float* __restrict__ embed) {
    __shared__ float tile[32][33];
    int bx = blockIdx.x, by = blockIdx.y;
    int tx = threadIdx.x, ty = threadIdx.y;
    tile[ty][tx] = embed[(size_t)(by * 32 + ty) * NCODES + bx * 32 + tx];
    __syncthreads();
    float v = tile[tx][ty];
    int n = bx * 32 + ty, k = by * 32 + tx;
    size_t o = (size_t)n * K_DIM + k;
    g_embT[o] = v;
    __nv_bfloat16 h = __float2bfloat16_rn(v);
    g_ebf_hi[o] = h;
    g_ebf_lo[o] = __float2bfloat16_rn(v - __bfloat162float(h));
}

__global__ void xsplit_kernel(const float* __restrict__ x) {
    int i = blockIdx.x * blockDim.x + threadIdx.x;   // float4 index
    float4 v = reinterpret_cast<const float4*>(x)[i];
    __nv_bfloat16 h0 = __float2bfloat16_rn(v.x), h1 = __float2bfloat16_rn(v.y);
    __nv_bfloat16 h2 = __float2bfloat16_rn(v.z), h3 = __float2bfloat16_rn(v.w);
    unsigned hw0 = (unsigned)__bfloat16_as_ushort(h0) | ((unsigned)__bfloat16_as_ushort(h1) << 16);
    unsigned hw1 = (unsigned)__bfloat16_as_ushort(h2) | ((unsigned)__bfloat16_as_ushort(h3) << 16);
    __nv_bfloat16 l0 = __float2bfloat16_rn(v.x - __bfloat162float(h0));
    __nv_bfloat16 l1 = __float2bfloat16_rn(v.y - __bfloat162float(h1));
    __nv_bfloat16 l2 = __float2bfloat16_rn(v.z - __bfloat162float(h2));
    __nv_bfloat16 l3 = __float2bfloat16_rn(v.w - __bfloat162float(h3));
    unsigned lw0 = (unsigned)__bfloat16_as_ushort(l0) | ((unsigned)__bfloat16_as_ushort(l1) << 16);
    unsigned lw1 = (unsigned)__bfloat16_as_ushort(l2) | ((unsigned)__bfloat16_as_ushort(l3) << 16);
    reinterpret_cast<uint2*>(g_xhi)[i] = make_uint2(hw0, hw1);
    reinterpret_cast<uint2*>(g_xlo)[i] = make_uint2(lw0, lw1);
}

// ---------------------------------------------------------------------------
// fused bf16x3 HMMA GEMM + per-stripe top-4
// ---------------------------------------------------------------------------
extern __shared__ char smc[];

__device__ __forceinline__ void issue_chunk(uint32_t smem, int c, int tid, int nstart) {
    int t = c >> 3, sub = c & 7;
    int kc = sub & 3;
    const char* base = (const char*)((sub < 4) ? g_ebf_hi : g_ebf_lo)
                     + ((size_t)(nstart + t * NT) * K_DIM + kc * 64) * 2;
    uint32_t dst = smem + SM_B + (uint32_t)(c & 3) * B_STAGE_B;
    #pragma unroll
    for (int j = 0; j < 2; j++) {
        int i = tid + j * THREADS;          // 0..1023
        int n = i >> 3, ch = i & 7;
        cpa16(dst + n * B_STRIDE_B + ch * 16, base + (size_t)n * 512 + ch * 16);
    }
}

__global__ void __launch_bounds__(THREADS, 1)
score_kernel() {
    const int tid = threadIdx.x;
    const int lane = tid & 31;
    const int warp = tid >> 5;
    const int mwarp = warp >> 2;            // 0..3
    const int nwarp = warp & 3;             // 0..3
    const int r0 = blockIdx.x * MT;
    const int nstart = blockIdx.y * STRIPE;
    const uint32_t smem = smem_u32(smc);

    // ---- prologue: A (hi+lo) + hesq stripe, then 2 B chunks ----
    {
        const char* xh = (const char*)g_xhi + (size_t)r0 * 512;
        const char* xl = (const char*)g_xlo + (size_t)r0 * 512;
        for (int i = tid; i < 128 * 32; i += THREADS) {
            int row = i >> 5, ch = i & 31;
            cpa16(smem + SM_AHI + row * A_STRIDE_B + ch * 16, xh + (size_t)row * 512 + ch * 16);
            cpa16(smem + SM_ALO + row * A_STRIDE_B + ch * 16, xl + (size_t)row * 512 + ch * 16);
        }
        for (int i = tid; i < 512; i += THREADS)
            cpa16(smem + SM_HESQ + i * 16, g_hesq + nstart + i * 4);
        CP_COMMIT();
        issue_chunk(smem, 0, tid, nstart); CP_COMMIT();
        issue_chunk(smem, 1, tid, nstart); CP_COMMIT();
    }

    float acc[2][4][4];                     // [m16 half][n8 block][frag]
    float tv[4][4];
    unsigned ti[4][4];
    #pragma unroll
    for (int r = 0; r < 4; r++)
        #pragma unroll
        for (int j = 0; j < 4; j++) { tv[r][j] = 3.4e38f; ti[r][j] = 0; }

    const uint32_t a_lane = (uint32_t)((lane & 15) * A_STRIDE_B + (lane >> 4) * 16);
    const uint32_t b_lane = (uint32_t)((lane & 15) * B_STRIDE_B + (lane >> 4) * 16);
    const uint32_t aHi = smem + SM_AHI + mwarp * 32 * A_STRIDE_B + a_lane;
    const uint32_t aLo = aHi + (SM_ALO - SM_AHI);
    const float* hesq_s = (const float*)(smc + SM_HESQ);

    for (int c = 0; c < CHUNKS; c++) {
        if (c + 2 < CHUNKS) issue_chunk(smem, c + 2, tid, nstart);
        CP_COMMIT();
        CP_WAIT2();
        __syncthreads();

        const int sub = c & 7;
        const int hi = (sub < 4);
        const int kc = sub & 3;
        const uint32_t kbyte = (uint32_t)kc * 128;
        const uint32_t Bb = smem + SM_B + (uint32_t)(c & 3) * B_STAGE_B
                          + (uint32_t)(nwarp * 32) * B_STRIDE_B + b_lane;

        if (sub == 0) {                     // new tile: clear accumulators
            #pragma unroll
            for (int ms = 0; ms < 2; ms++)
                #pragma unroll
                for (int ns = 0; ns < 4; ns++)
                    #pragma unroll
                    for (int j = 0; j < 4; j++) acc[ms][ns][j] = 0.f;
        }

        #pragma unroll
        for (int ks = 0; ks < 4; ks++) {
            const uint32_t koff = kbyte + ks * 32;
            uint32_t bf[2][4];
            ldm4(bf[0], Bb + ks * 32);
            ldm4(bf[1], Bb + ks * 32 + 16 * B_STRIDE_B);
            uint32_t ah0[4], ah1[4];
            ldm4(ah0, aHi + koff);
            ldm4(ah1, aHi + 16 * A_STRIDE_B + koff);
            if (hi) {
                uint32_t al0[4], al1[4];
                ldm4(al0, aLo + koff);
                ldm4(al1, aLo + 16 * A_STRIDE_B + koff);
                // all 8 independent ah-MMAs first, then al-MMAs (RAW distance 8)
                #pragma unroll
                for (int ns = 0; ns < 4; ns++) {
                    uint32_t b0 = bf[ns >> 1][ns & 1], b1 = bf[ns >> 1][(ns & 1) + 2];
                    mma_bf16(acc[0][ns], ah0, b0, b1);
                    mma_bf16(acc[1][ns], ah1, b0, b1);
                }
                #pragma unroll
                for (int ns = 0; ns < 4; ns++) {
                    uint32_t b0 = bf[ns >> 1][ns & 1], b1 = bf[ns >> 1][(ns & 1) + 2];
                    mma_bf16(acc[0][ns], al0, b0, b1);
                    mma_bf16(acc[1][ns], al1, b0, b1);
                }
            } else {
                #pragma unroll
                for (int ns = 0; ns < 4; ns++) {
                    uint32_t b0 = bf[ns >> 1][ns & 1], b1 = bf[ns >> 1][(ns & 1) + 2];
                    mma_bf16(acc[0][ns], ah0, b0, b1);
                    mma_bf16(acc[1][ns], ah1, b0, b1);
                }
            }
        }

        if (sub == 7) {                     // tile done: score + top-4
            const int t = c >> 3;
            const int colbase = t * NT + nwarp * 32 + (lane & 3) * 2;
            #pragma unroll
            for (int ms = 0; ms < 2; ms++)
                #pragma unroll
                for (int ns = 0; ns < 4; ns++)
                    #pragma unroll
                    for (int i = 0; i < 4; i++) {
                        int col = colbase + ns * 8 + (i & 1);
                        float s = hesq_s[col] - acc[ms][ns][i];
                        const int rid = ms * 2 + (i >> 1);
                        if (s < tv[rid][3]) {
                            unsigned n = (unsigned)(nstart + col);
                            if (s < tv[rid][0]) {
                                tv[rid][3]=tv[rid][2]; ti[rid][3]=ti[rid][2];
                                tv[rid][2]=tv[rid][1]; ti[rid][2]=ti[rid][1];
                                tv[rid][1]=tv[rid][0]; ti[rid][1]=ti[rid][0];
                                tv[rid][0]=s; ti[rid][0]=n;
                            } else if (s < tv[rid][1]) {
                                tv[rid][3]=tv[rid][2]; ti[rid][3]=ti[rid][2];
                                tv[rid][2]=tv[rid][1]; ti[rid][2]=ti[rid][1];
                                tv[rid][1]=s; ti[rid][1]=n;
                            } else if (s < tv[rid][2]) {
                                tv[rid][3]=tv[rid][2]; ti[rid][3]=ti[rid][2];
                                tv[rid][2]=s; ti[rid][2]=n;
                            } else { tv[rid][3]=s; ti[rid][3]=n; }
                        }
                    }
        }
        __syncthreads();
    }

    // ---- per-CTA merge: 16 partial top-4 lists per row -> stripe top-4 ----
    char* scr = smc + SM_MERGE;
    const int slot = nwarp * 4 + (lane & 3);
    #pragma unroll
    for (int rid = 0; rid < 4; rid++) {
        int row = mwarp * 32 + (rid >> 1) * 16 + (rid & 1) * 8 + (lane >> 2);
        char* p = scr + (row * 16 + slot) * 32;
        *reinterpret_cast<float4*>(p)      = make_float4(tv[rid][0], tv[rid][1], tv[rid][2], tv[rid][3]);
        *reinterpret_cast<uint4*>(p + 16)  = make_uint4(ti[rid][0], ti[rid][1], ti[rid][2], ti[rid][3]);
    }
    __syncthreads();

    if (tid < MT) {
        float v[4] = {3.4e38f, 3.4e38f, 3.4e38f, 3.4e38f};
        unsigned id[4] = {0, 0, 0, 0};
        const char* p = scr + tid * 16 * 32;
        for (int s = 0; s < 16; s++) {
            float4 pv = *reinterpret_cast<const float4*>(p + s * 32);
            uint4  pi = *reinterpret_cast<const uint4*>(p + s * 32 + 16);
            float cv[4] = {pv.x, pv.y, pv.z, pv.w};
            unsigned ci[4] = {pi.x, pi.y, pi.z, pi.w};
            #pragma unroll
            for (int j = 0; j < 4; j++) {
                float s1 = cv[j]; unsigned n1 = ci[j];
                if (s1 < v[3] || (s1 == v[3] && n1 < id[3])) {
                    if (s1 < v[0] || (s1 == v[0] && n1 < id[0])) {
                        v[3]=v[2];id[3]=id[2]; v[2]=v[1];id[2]=id[1]; v[1]=v[0];id[1]=id[0]; v[0]=s1;id[0]=n1;
                    } else if (s1 < v[1] || (s1 == v[1] && n1 < id[1])) {
                        v[3]=v[2];id[3]=id[2]; v[2]=v[1];id[2]=id[1]; v[1]=s1;id[1]=n1;
                    } else if (s1 < v[2] || (s1 == v[2] && n1 < id[2])) {
                        v[3]=v[2];id[3]=id[2]; v[2]=s1;id[2]=n1;
                    } else { v[3]=s1; id[3]=n1; }
                }
            }
        }
        g_pvals[blockIdx.y][r0 + tid] = make_float4(v[0], v[1], v[2], v[3]);
        g_pidx[blockIdx.y][r0 + tid]  = make_uint4(id[0], id[1], id[2], id[3]);
    }
}

// ---------------------------------------------------------------------------
// merge stripes + certify + exact candidate rescore
// ---------------------------------------------------------------------------
__global__ void merge_kernel(const float* __restrict__ x) {
    int r = blockIdx.x * blockDim.x + threadIdx.x;
    float v[4] = {3.4e38f, 3.4e38f, 3.4e38f, 3.4e38f};
    unsigned id[4] = {0, 0, 0, 0};
    float L = 3.4e38f;
    float allv[16]; unsigned alli[16];
    #pragma unroll
    for (int s = 0; s < NSPLIT; s++) {
        float4 pv = g_pvals[s][r];
        uint4  pi = g_pidx[s][r];
        if (pv.w < L) L = pv.w;
        float cv[4] = {pv.x, pv.y, pv.z, pv.w};
        unsigned ci[4] = {pi.x, pi.y, pi.z, pi.w};
        #pragma unroll
        for (int j = 0; j < 4; j++) {
            allv[s * 4 + j] = cv[j]; alli[s * 4 + j] = ci[j];
            float s1 = cv[j]; unsigned n1 = ci[j];
            if (s1 < v[3] || (s1 == v[3] && n1 < id[3])) {
                if (s1 < v[0] || (s1 == v[0] && n1 < id[0])) {
                    v[3]=v[2];id[3]=id[2]; v[2]=v[1];id[2]=id[1]; v[1]=v[0];id[1]=id[0]; v[0]=s1;id[0]=n1;
                } else if (s1 < v[1] || (s1 == v[1] && n1 < id[1])) {
                    v[3]=v[2];id[3]=id[2]; v[2]=v[1];id[2]=id[1]; v[1]=s1;id[1]=n1;
                } else if (s1 < v[2] || (s1 == v[2] && n1 < id[2])) {
                    v[3]=v[2];id[3]=id[2]; v[2]=s1;id[2]=n1;
                } else { v[3]=s1; id[3]=n1; }
            }
        }
    }
    if (v[1] - v[0] >= TAU) { g_idx[r] = id[0]; return; }

    // exact fp32 rescore of all 16 candidates
    const float4* xv = reinterpret_cast<const float4*>(x + (size_t)r * K_DIM);
    float best = 3.4e38f; unsigned bi = 0xFFFFFFFFu;
    for (int j = 0; j < 16; j++) {
        unsigned n = alli[j];
        const float4* er = reinterpret_cast<const float4*>(g_embT + (size_t)n * K_DIM);
        float dot = 0.f;
        #pragma unroll 8
        for (int k = 0; k < K_DIM / 4; k++) {
            float4 a = xv[k], b = er[k];
            dot += a.x * b.x + a.y * b.y + a.z * b.z + a.w * b.w;
        }
        float s = g_hesq[n] - dot;
        if (s < best || (s == best && n < bi)) { best = s; bi = n; }
    }
    g_idx[r] = bi;
    if (L - v[0] < TAU) {              // candidate set not certified complete
        int p = atomicAdd(&g_nflag, 1);
        g_flag[p] = r;
    }
}

// ---------------------------------------------------------------------------
// full exact argmin for rare uncertified rows
// ---------------------------------------------------------------------------
__global__ void fixup_full_kernel(const float* __restrict__ x) {
    __shared__ float xs[K_DIM];
    __shared__ float wv[8];
    __shared__ unsigned wi[8];
    int nf = g_nflag;
    for (int f = blockIdx.x; f < nf; f += gridDim.x) {
        int r = g_flag[f];
        for (int k = threadIdx.x; k < K_DIM; k += blockDim.x) xs[k] = x[(size_t)r * K_DIM + k];
        __syncthreads();
        float best = 3.4e38f; unsigned bi = 0xFFFFFFFFu;
        for (int n = threadIdx.x; n < NCODES; n += blockDim.x) {
            const float4* er = reinterpret_cast<const float4*>(g_embT + (size_t)n * K_DIM);
            float dot = 0.f;
            #pragma unroll 8
            for (int k = 0; k < K_DIM / 4; k++) {
                float4 b = er[k];
                dot += xs[4*k] * b.x + xs[4*k+1] * b.y + xs[4*k+2] * b.z + xs[4*k+3] * b.w;
            }
            float s = g_hesq[n] - dot;
            if (s < best || (s == best && n < bi)) { best = s; bi = n; }
        }
        #pragma unroll
        for (int off = 16; off > 0; off >>= 1) {
            float ov = __shfl_down_sync(0xffffffffu, best, off);
            unsigned oi = __shfl_down_sync(0xffffffffu, bi, off);
            if (ov < best || (ov == best && oi < bi)) { best = ov; bi = oi; }
        }
        if ((threadIdx.x & 31) == 0) { wv[threadIdx.x >> 5] = best; wi[threadIdx.x >> 5] = bi; }
        __syncthreads();
        if (threadIdx.x == 0) {
            for (int w = 1; w < 8; w++)
                if (wv[w] < best || (wv[w] == best && wi[w] < bi)) { best = wv[w]; bi = wi[w]; }
            g_idx[r] = bi;
        }
        __syncthreads();
    }
}

// ---------------------------------------------------------------------------
__global__ void gather_kernel(float* __restrict__ out) {
    int r = blockIdx.x * 4 + (threadIdx.x >> 6);
    int c = threadIdx.x & 63;
    unsigned idx = g_idx[r] & (NCODES - 1);
    const float4* src = reinterpret_cast<const float4*>(g_embT + (size_t)idx * K_DIM);
    reinterpret_cast<float4*>(out + (size_t)r * K_DIM)[c] = src[c];
}

// ---------------------------------------------------------------------------
extern "C" void kernel_launch(void* const* d_in, const int* in_sizes, int n_in,
                              void* d_out, int out_size) {
    const float* x = (const float*)d_in[0];      // [32768, 256]
    const float* embed = (const float*)d_in[1];  // [256, 8192]
    float* out = (float*)d_out;

    cudaFuncSetAttribute(score_kernel, cudaFuncAttributeMaxDynamicSharedMemorySize,
                         SMEM_TOTAL);

    prep_kernel<<<NCODES / 256, 256>>>(embed);
    transpose_split_kernel<<<dim3(NCODES / 32, K_DIM / 32), dim3(32, 32)>>>(embed);
    xsplit_kernel<<<(M_TOTAL * K_DIM / 4) / 256, 256>>>(x);
    score_kernel<<<dim3(M_TOTAL / MT, NSPLIT), THREADS, SMEM_TOTAL>>>();
    merge_kernel<<<M_TOTAL / 256, 256>>>(x);
    fixup_full_kernel<<<32, 256>>>(x);
    gather_kernel<<<M_TOTAL / 4, 256>>>(out);
}

// round 9
// speedup vs baseline: 2.8205x; 1.3508x over previous
#include <cuda_runtime.h>
#include <cuda_bf16.h>
#include <cstdint>

#define M_TOTAL 32768
#define K_DIM   256
#define NCODES  8192
#define MT      128
#define NSPLIT  4
#define STRIPE  2048
#define NT      128
#define NTILES  16
#define CHUNKS  32            // 16 tiles * 2 half-k chunks
#define THREADS 256
#define TAU     1.25f

// SMEM layout (bytes)
#define A_STRIDE_B  528       // 256 bf16 + 8 pad
#define B_STRIDE_B  272       // 128 bf16 + 8 pad
#define SM_A        0         // 128*528 = 67584
#define SM_B        67584     // 4 stages * 34816 = 139264
#define B_STAGE_B   34816
#define SM_HESQ     206848    // 2048 floats = 8192
#define SMEM_TOTAL  215040
#define SM_MERGE    SM_B      // reuse stage 0 after main loop (128*8*32 = 32768)

// device globals
__device__ float          g_hesq[NCODES];
__device__ float          g_embT[(size_t)NCODES * K_DIM];
__device__ __nv_bfloat16  g_ebf[(size_t)NCODES * K_DIM];
__device__ __nv_bfloat16  g_xbf[(size_t)M_TOTAL * K_DIM];
__device__ float4         g_pvals[NSPLIT][M_TOTAL];
__device__ uint4          g_pidx[NSPLIT][M_TOTAL];
__device__ unsigned       g_idx[M_TOTAL];
__device__ int            g_nflag;
__device__ int            g_flag[M_TOTAL];

// ---- helpers -------------------------------------------------------------
__device__ __forceinline__ uint32_t smem_u32(const void* p) {
    uint32_t a;
    asm("{ .reg .u64 t; cvta.to.shared.u64 t, %1; cvt.u32.u64 %0, t; }" : "=r"(a) : "l"(p));
    return a;
}
__device__ __forceinline__ void cpa16(uint32_t dst, const void* src) {
    asm volatile("cp.async.cg.shared.global [%0], [%1], 16;" :: "r"(dst), "l"(src));
}
#define CP_COMMIT() asm volatile("cp.async.commit_group;" ::: "memory")
#define CP_WAIT2()  asm volatile("cp.async.wait_group 2;" ::: "memory")

__device__ __forceinline__ void ldm4(uint32_t* r, uint32_t addr) {
    asm volatile("ldmatrix.sync.aligned.m8n8.x4.shared.b16 {%0,%1,%2,%3}, [%4];"
                 : "=r"(r[0]), "=r"(r[1]), "=r"(r[2]), "=r"(r[3]) : "r"(addr));
}
__device__ __forceinline__ void mma_bf16(float* d, const uint32_t* a, uint32_t b0, uint32_t b1) {
    asm volatile("mma.sync.aligned.m16n8k16.row.col.f32.bf16.bf16.f32 "
                 "{%0,%1,%2,%3},{%4,%5,%6,%7},{%8,%9},{%0,%1,%2,%3};"
                 : "+f"(d[0]), "+f"(d[1]), "+f"(d[2]), "+f"(d[3])
                 : "r"(a[0]), "r"(a[1]), "r"(a[2]), "r"(a[3]), "r"(b0), "r"(b1));
}

// ---------------------------------------------------------------------------
// prep kernels
// ---------------------------------------------------------------------------
__global__ void prep_kernel(const float* __restrict__ embed) {
    int n = blockIdx.x * blockDim.x + threadIdx.x;
    if (n == 0) g_nflag = 0;
    if (n < NCODES) {
        float s = 0.f;
        #pragma unroll 8
        for (int k = 0; k < K_DIM; k++) {
            float v = embed[(size_t)k * NCODES + n];
            s += v * v;
        }
        g_hesq[n] = 0.5f * s;
    }
}

__global__ void transpose_split_kernel(const float* __restrict__ embed) {
    __shared__ float tile[32][33];
    int bx = blockIdx.x, by = blockIdx.y;
    int tx = threadIdx.x, ty = threadIdx.y;
    tile[ty][tx] = embed[(size_t)(by * 32 + ty) * NCODES + bx * 32 + tx];
    __syncthreads();
    float v = tile[tx][ty];
    int n = bx * 32 + ty, k = by * 32 + tx;
    size_t o = (size_t)n * K_DIM + k;
    g_embT[o] = v;
    g_ebf[o] = __float2bfloat16_rn(v);
}

__global__ void xsplit_kernel(const float* __restrict__ x) {
    int i = blockIdx.x * blockDim.x + threadIdx.x;   // float4 index
    float4 v = reinterpret_cast<const float4*>(x)[i];
    unsigned hw0 = (unsigned)__bfloat16_as_ushort(__float2bfloat16_rn(v.x))
                 | ((unsigned)__bfloat16_as_ushort(__float2bfloat16_rn(v.y)) << 16);
    unsigned hw1 = (unsigned)__bfloat16_as_ushort(__float2bfloat16_rn(v.z))
                 | ((unsigned)__bfloat16_as_ushort(__float2bfloat16_rn(v.w)) << 16);
    reinterpret_cast<uint2*>(g_xbf)[i] = make_uint2(hw0, hw1);
}

// ---------------------------------------------------------------------------
// fused bf16 HMMA filter GEMM + per-stripe top-4
// ---------------------------------------------------------------------------
extern __shared__ char smc[];

__device__ __forceinline__ void issue_chunk(uint32_t smem, int c, int tid, int nstart) {
    int t = c >> 1, h = c & 1;
    const char* base = (const char*)g_ebf
                     + (size_t)(nstart + t * NT) * 512 + h * 256;
    uint32_t dst = smem + SM_B + (uint32_t)(c & 3) * B_STAGE_B;
    #pragma unroll
    for (int j = 0; j < 8; j++) {
        int i = tid + j * THREADS;          // 0..2047
        int n = i >> 4, ch = i & 15;
        cpa16(dst + n * B_STRIDE_B + ch * 16, base + (size_t)n * 512 + ch * 16);
    }
}

__global__ void __launch_bounds__(THREADS, 1)
score_kernel() {
    const int tid = threadIdx.x;
    const int lane = tid & 31;
    const int warp = tid >> 5;
    const int mwarp = warp >> 1;            // 0..3 (32 rows each)
    const int nwarp = warp & 1;             // 0..1 (64 cols each)
    const int r0 = blockIdx.x * MT;
    const int nstart = blockIdx.y * STRIPE;
    const uint32_t smem = smem_u32(smc);

    // ---- prologue: A + hesq stripe, then 2 B chunks ----
    {
        const char* xh = (const char*)g_xbf + (size_t)r0 * 512;
        #pragma unroll
        for (int j = 0; j < 16; j++) {
            int i = tid + j * THREADS;      // 0..4095
            int row = i >> 5, ch = i & 31;
            cpa16(smem + SM_A + row * A_STRIDE_B + ch * 16, xh + (size_t)row * 512 + ch * 16);
        }
        for (int i = tid; i < 512; i += THREADS)
            cpa16(smem + SM_HESQ + i * 16, g_hesq + nstart + i * 4);
        CP_COMMIT();
        issue_chunk(smem, 0, tid, nstart); CP_COMMIT();
        issue_chunk(smem, 1, tid, nstart); CP_COMMIT();
    }

    float acc[2][8][4];                     // [m16 half][n8 block][frag]
    float tv[4][4];
    unsigned ti[4][4];
    #pragma unroll
    for (int r = 0; r < 4; r++)
        #pragma unroll
        for (int j = 0; j < 4; j++) { tv[r][j] = 3.4e38f; ti[r][j] = 0; }

    const uint32_t a_lane = (uint32_t)((lane & 15) * A_STRIDE_B + (lane >> 4) * 16);
    const uint32_t b_lane = (uint32_t)((lane & 15) * B_STRIDE_B + (lane >> 4) * 16);
    const uint32_t aBase = smem + SM_A + mwarp * 32 * A_STRIDE_B + a_lane;
    const float* hesq_s = (const float*)(smc + SM_HESQ);

    for (int c = 0; c < CHUNKS; c++) {
        if (c + 2 < CHUNKS) issue_chunk(smem, c + 2, tid, nstart);
        CP_COMMIT();
        CP_WAIT2();
        __syncthreads();

        const int h = c & 1;
        const uint32_t aCh = aBase + (uint32_t)h * 256;   // k offset of this chunk
        const uint32_t Bb = smem + SM_B + (uint32_t)(c & 3) * B_STAGE_B
                          + (uint32_t)(nwarp * 64) * B_STRIDE_B + b_lane;

        if (h == 0) {
            #pragma unroll
            for (int ms = 0; ms < 2; ms++)
                #pragma unroll
                for (int ns = 0; ns < 8; ns++)
                    #pragma unroll
                    for (int j = 0; j < 4; j++) acc[ms][ns][j] = 0.f;
        }

        // software-pipelined fragment double buffer over 8 k16 steps
        uint32_t bf[2][4][4], af[2][2][4];
        ldm4(bf[0][0], Bb);
        ldm4(bf[0][1], Bb + 16 * B_STRIDE_B);
        ldm4(bf[0][2], Bb + 32 * B_STRIDE_B);
        ldm4(bf[0][3], Bb + 48 * B_STRIDE_B);
        ldm4(af[0][0], aCh);
        ldm4(af[0][1], aCh + 16 * A_STRIDE_B);

        #pragma unroll
        for (int ks = 0; ks < 8; ks++) {
            const int cur = ks & 1, nxt = cur ^ 1;
            if (ks < 7) {
                const uint32_t ko = (ks + 1) * 32;
                ldm4(bf[nxt][0], Bb + ko);
                ldm4(bf[nxt][1], Bb + ko + 16 * B_STRIDE_B);
                ldm4(bf[nxt][2], Bb + ko + 32 * B_STRIDE_B);
                ldm4(bf[nxt][3], Bb + ko + 48 * B_STRIDE_B);
                ldm4(af[nxt][0], aCh + ko);
                ldm4(af[nxt][1], aCh + ko + 16 * A_STRIDE_B);
            }
            #pragma unroll
            for (int ns = 0; ns < 8; ns++) {
                uint32_t b0 = bf[cur][ns >> 1][ns & 1];
                uint32_t b1 = bf[cur][ns >> 1][(ns & 1) + 2];
                mma_bf16(acc[0][ns], af[cur][0], b0, b1);
                mma_bf16(acc[1][ns], af[cur][1], b0, b1);
            }
        }

        if (h == 1) {                        // tile done: score + top-4
            const int t = c >> 1;
            const int colbase = t * NT + nwarp * 64 + (lane & 3) * 2;
            #pragma unroll
            for (int ms = 0; ms < 2; ms++)
                #pragma unroll
                for (int ns = 0; ns < 8; ns++)
                    #pragma unroll
                    for (int i = 0; i < 4; i++) {
                        int col = colbase + ns * 8 + (i & 1);
                        float s = hesq_s[col] - acc[ms][ns][i];
                        const int rid = ms * 2 + (i >> 1);
                        if (s < tv[rid][3]) {
                            unsigned n = (unsigned)(nstart + col);
                            if (s < tv[rid][0]) {
                                tv[rid][3]=tv[rid][2]; ti[rid][3]=ti[rid][2];
                                tv[rid][2]=tv[rid][1]; ti[rid][2]=ti[rid][1];
                                tv[rid][1]=tv[rid][0]; ti[rid][1]=ti[rid][0];
                                tv[rid][0]=s; ti[rid][0]=n;
                            } else if (s < tv[rid][1]) {
                                tv[rid][3]=tv[rid][2]; ti[rid][3]=ti[rid][2];
                                tv[rid][2]=tv[rid][1]; ti[rid][2]=ti[rid][1];
                                tv[rid][1]=s; ti[rid][1]=n;
                            } else if (s < tv[rid][2]) {
                                tv[rid][3]=tv[rid][2]; ti[rid][3]=ti[rid][2];
                                tv[rid][2]=s; ti[rid][2]=n;
                            } else { tv[rid][3]=s; ti[rid][3]=n; }
                        }
                    }
        }
    }

    // ---- per-CTA merge: 8 partial top-4 lists per row -> stripe top-4 ----
    char* scr = smc + SM_MERGE;
    const int slot = nwarp * 4 + (lane & 3);
    #pragma unroll
    for (int rid = 0; rid < 4; rid++) {
        int row = mwarp * 32 + (rid >> 1) * 16 + (rid & 1) * 8 + (lane >> 2);
        char* p = scr + (row * 8 + slot) * 32;
        *reinterpret_cast<float4*>(p)      = make_float4(tv[rid][0], tv[rid][1], tv[rid][2], tv[rid][3]);
        *reinterpret_cast<uint4*>(p + 16)  = make_uint4(ti[rid][0], ti[rid][1], ti[rid][2], ti[rid][3]);
    }
    __syncthreads();

    if (tid < MT) {
        float v[4] = {3.4e38f, 3.4e38f, 3.4e38f, 3.4e38f};
        unsigned id[4] = {0, 0, 0, 0};
        const char* p = scr + tid * 8 * 32;
        for (int s = 0; s < 8; s++) {
            float4 pv = *reinterpret_cast<const float4*>(p + s * 32);
            uint4  pi = *reinterpret_cast<const uint4*>(p + s * 32 + 16);
            float cv[4] = {pv.x, pv.y, pv.z, pv.w};
            unsigned ci[4] = {pi.x, pi.y, pi.z, pi.w};
            #pragma unroll
            for (int j = 0; j < 4; j++) {
                float s1 = cv[j]; unsigned n1 = ci[j];
                if (s1 < v[3] || (s1 == v[3] && n1 < id[3])) {
                    if (s1 < v[0] || (s1 == v[0] && n1 < id[0])) {
                        v[3]=v[2];id[3]=id[2]; v[2]=v[1];id[2]=id[1]; v[1]=v[0];id[1]=id[0]; v[0]=s1;id[0]=n1;
                    } else if (s1 < v[1] || (s1 == v[1] && n1 < id[1])) {
                        v[3]=v[2];id[3]=id[2]; v[2]=v[1];id[2]=id[1]; v[1]=s1;id[1]=n1;
                    } else if (s1 < v[2] || (s1 == v[2] && n1 < id[2])) {
                        v[3]=v[2];id[3]=id[2]; v[2]=s1;id[2]=n1;
                    } else { v[3]=s1; id[3]=n1; }
                }
            }
        }
        g_pvals[blockIdx.y][r0 + tid] = make_float4(v[0], v[1], v[2], v[3]);
        g_pidx[blockIdx.y][r0 + tid]  = make_uint4(id[0], id[1], id[2], id[3]);
    }
}

// ---------------------------------------------------------------------------
// merge stripes + certify + exact candidate rescore
// ---------------------------------------------------------------------------
__global__ void merge_kernel(const float* __restrict__ x) {
    int r = blockIdx.x * blockDim.x + threadIdx.x;
    float v[4] = {3.4e38f, 3.4e38f, 3.4e38f, 3.4e38f};
    unsigned id[4] = {0, 0, 0, 0};
    float L = 3.4e38f;
    unsigned alli[16];
    #pragma unroll
    for (int s = 0; s < NSPLIT; s++) {
        float4 pv = g_pvals[s][r];
        uint4  pi = g_pidx[s][r];
        if (pv.w < L) L = pv.w;
        float cv[4] = {pv.x, pv.y, pv.z, pv.w};
        unsigned ci[4] = {pi.x, pi.y, pi.z, pi.w};
        #pragma unroll
        for (int j = 0; j < 4; j++) {
            alli[s * 4 + j] = ci[j];
            float s1 = cv[j]; unsigned n1 = ci[j];
            if (s1 < v[3] || (s1 == v[3] && n1 < id[3])) {
                if (s1 < v[0] || (s1 == v[0] && n1 < id[0])) {
                    v[3]=v[2];id[3]=id[2]; v[2]=v[1];id[2]=id[1]; v[1]=v[0];id[1]=id[0]; v[0]=s1;id[0]=n1;
                } else if (s1 < v[1] || (s1 == v[1] && n1 < id[1])) {
                    v[3]=v[2];id[3]=id[2]; v[2]=v[1];id[2]=id[1]; v[1]=s1;id[1]=n1;
                } else if (s1 < v[2] || (s1 == v[2] && n1 < id[2])) {
                    v[3]=v[2];id[3]=id[2]; v[2]=s1;id[2]=n1;
                } else { v[3]=s1; id[3]=n1; }
            }
        }
    }
    if (v[1] - v[0] >= TAU) { g_idx[r] = id[0]; return; }

    // exact fp32 rescore of all 16 candidates
    const float4* xv = reinterpret_cast<const float4*>(x + (size_t)r * K_DIM);
    float best = 3.4e38f; unsigned bi = 0xFFFFFFFFu;
    for (int j = 0; j < 16; j++) {
        unsigned n = alli[j];
        const float4* er = reinterpret_cast<const float4*>(g_embT + (size_t)n * K_DIM);
        float dot = 0.f;
        #pragma unroll 8
        for (int k = 0; k < K_DIM / 4; k++) {
            float4 a = xv[k], b = er[k];
            dot += a.x * b.x + a.y * b.y + a.z * b.z + a.w * b.w;
        }
        float s = g_hesq[n] - dot;
        if (s < best || (s == best && n < bi)) { best = s; bi = n; }
    }
    g_idx[r] = bi;
    if (L - v[0] < TAU) {              // candidate set not certified complete
        int p = atomicAdd(&g_nflag, 1);
        g_flag[p] = r;
    }
}

// ---------------------------------------------------------------------------
// full exact argmin for rare uncertified rows
// ---------------------------------------------------------------------------
__global__ void fixup_full_kernel(const float* __restrict__ x) {
    __shared__ float xs[K_DIM];
    __shared__ float wv[8];
    __shared__ unsigned wi[8];
    int nf = g_nflag;
    for (int f = blockIdx.x; f < nf; f += gridDim.x) {
        int r = g_flag[f];
        for (int k = threadIdx.x; k < K_DIM; k += blockDim.x) xs[k] = x[(size_t)r * K_DIM + k];
        __syncthreads();
        float best = 3.4e38f; unsigned bi = 0xFFFFFFFFu;
        for (int n = threadIdx.x; n < NCODES; n += blockDim.x) {
            const float4* er = reinterpret_cast<const float4*>(g_embT + (size_t)n * K_DIM);
            float dot = 0.f;
            #pragma unroll 8
            for (int k = 0; k < K_DIM / 4; k++) {
                float4 b = er[k];
                dot += xs[4*k] * b.x + xs[4*k+1] * b.y + xs[4*k+2] * b.z + xs[4*k+3] * b.w;
            }
            float s = g_hesq[n] - dot;
            if (s < best || (s == best && n < bi)) { best = s; bi = n; }
        }
        #pragma unroll
        for (int off = 16; off > 0; off >>= 1) {
            float ov = __shfl_down_sync(0xffffffffu, best, off);
            unsigned oi = __shfl_down_sync(0xffffffffu, bi, off);
            if (ov < best || (ov == best && oi < bi)) { best = ov; bi = oi; }
        }
        if ((threadIdx.x & 31) == 0) { wv[threadIdx.x >> 5] = best; wi[threadIdx.x >> 5] = bi; }
        __syncthreads();
        if (threadIdx.x == 0) {
            for (int w = 1; w < 8; w++)
                if (wv[w] < best || (wv[w] == best && wi[w] < bi)) { best = wv[w]; bi = wi[w]; }
            g_idx[r] = bi;
        }
        __syncthreads();
    }
}

// ---------------------------------------------------------------------------
__global__ void gather_kernel(float* __restrict__ out) {
    int r = blockIdx.x * 4 + (threadIdx.x >> 6);
    int c = threadIdx.x & 63;
    unsigned idx = g_idx[r] & (NCODES - 1);
    const float4* src = reinterpret_cast<const float4*>(g_embT + (size_t)idx * K_DIM);
    reinterpret_cast<float4*>(out + (size_t)r * K_DIM)[c] = src[c];
}

// ---------------------------------------------------------------------------
extern "C" void kernel_launch(void* const* d_in, const int* in_sizes, int n_in,
                              void* d_out, int out_size) {
    const float* x = (const float*)d_in[0];      // [32768, 256]
    const float* embed = (const float*)d_in[1];  // [256, 8192]
    float* out = (float*)d_out;

    cudaFuncSetAttribute(score_kernel, cudaFuncAttributeMaxDynamicSharedMemorySize,
                         SMEM_TOTAL);

    prep_kernel<<<NCODES / 256, 256>>>(embed);
    transpose_split_kernel<<<dim3(NCODES / 32, K_DIM / 32), dim3(32, 32)>>>(embed);
    xsplit_kernel<<<(M_TOTAL * K_DIM / 4) / 256, 256>>>(x);
    score_kernel<<<dim3(M_TOTAL / MT, NSPLIT), THREADS, SMEM_TOTAL>>>();
    merge_kernel<<<M_TOTAL / 256, 256>>>(x);
    fixup_full_kernel<<<32, 256>>>(x);
    gather_kernel<<<M_TOTAL / 4, 256>>>(out);
}

// round 10
// speedup vs baseline: 2.8995x; 1.0280x over previous
#include <cuda_runtime.h>
#include <cuda_bf16.h>
#include <cstdint>

#define M_TOTAL 32768
#define K_DIM   256
#define NCODES  8192
#define MT      128
#define NSPLIT  4
#define STRIPE  2048
#define NT      128
#define NTILES  16
#define CHUNKS  32            // 16 tiles * 2 half-k chunks
#define THREADS 512
#define TAU     0.4f

// SMEM layout (bytes)
#define A_STRIDE_B  528       // 256 bf16 + 8 pad
#define B_STRIDE_B  272       // 128 bf16 + 8 pad
#define SM_A        0         // 128*528 = 67584
#define SM_B        67584     // 4 stages * 34816 = 139264
#define B_STAGE_B   34816
#define SM_HESQ     206848    // 2048 floats = 8192
#define SMEM_TOTAL  215040
#define SM_MERGE    SM_B      // reuse B ring after main loop (128*16*32 = 65536)

// device globals
__device__ float          g_hesq[NCODES];
__device__ float          g_embT[(size_t)NCODES * K_DIM];
__device__ __nv_bfloat16  g_ebf[(size_t)NCODES * K_DIM];
__device__ __nv_bfloat16  g_xbf[(size_t)M_TOTAL * K_DIM];
__device__ float4         g_pvals[NSPLIT][M_TOTAL];
__device__ uint4          g_pidx[NSPLIT][M_TOTAL];
__device__ unsigned       g_idx[M_TOTAL];
__device__ int            g_nflag;
__device__ int            g_flag[M_TOTAL];

// ---- helpers -------------------------------------------------------------
__device__ __forceinline__ uint32_t smem_u32(const void* p) {
    uint32_t a;
    asm("{ .reg .u64 t; cvta.to.shared.u64 t, %1; cvt.u32.u64 %0, t; }" : "=r"(a) : "l"(p));
    return a;
}
__device__ __forceinline__ void cpa16(uint32_t dst, const void* src) {
    asm volatile("cp.async.cg.shared.global [%0], [%1], 16;" :: "r"(dst), "l"(src));
}
#define CP_COMMIT() asm volatile("cp.async.commit_group;" ::: "memory")
#define CP_WAIT2()  asm volatile("cp.async.wait_group 2;" ::: "memory")

__device__ __forceinline__ void ldm4(uint32_t* r, uint32_t addr) {
    asm volatile("ldmatrix.sync.aligned.m8n8.x4.shared.b16 {%0,%1,%2,%3}, [%4];"
                 : "=r"(r[0]), "=r"(r[1]), "=r"(r[2]), "=r"(r[3]) : "r"(addr));
}
__device__ __forceinline__ void mma_bf16(float* d, const uint32_t* a, uint32_t b0, uint32_t b1) {
    asm volatile("mma.sync.aligned.m16n8k16.row.col.f32.bf16.bf16.f32 "
                 "{%0,%1,%2,%3},{%4,%5,%6,%7},{%8,%9},{%0,%1,%2,%3};"
                 : "+f"(d[0]), "+f"(d[1]), "+f"(d[2]), "+f"(d[3])
                 : "r"(a[0]), "r"(a[1]), "r"(a[2]), "r"(a[3]), "r"(b0), "r"(b1));
}

// ---------------------------------------------------------------------------
// prep kernels
// ---------------------------------------------------------------------------
__global__ void prep_kernel(const float* __restrict__ embed) {
    int n = blockIdx.x * blockDim.x + threadIdx.x;
    if (n == 0) g_nflag = 0;
    if (n < NCODES) {
        float s = 0.f;
        #pragma unroll 8
        for (int k = 0; k < K_DIM; k++) {
            float v = embed[(size_t)k * NCODES + n];
            s += v * v;
        }
        g_hesq[n] = 0.5f * s;
    }
}

__global__ void transpose_split_kernel(const float* __restrict__ embed) {
    __shared__ float tile[32][33];
    int bx = blockIdx.x, by = blockIdx.y;
    int tx = threadIdx.x, ty = threadIdx.y;
    tile[ty][tx] = embed[(size_t)(by * 32 + ty) * NCODES + bx * 32 + tx];
    __syncthreads();
    float v = tile[tx][ty];
    int n = bx * 32 + ty, k = by * 32 + tx;
    size_t o = (size_t)n * K_DIM + k;
    g_embT[o] = v;
    g_ebf[o] = __float2bfloat16_rn(v);
}

__global__ void xsplit_kernel(const float* __restrict__ x) {
    int i = blockIdx.x * blockDim.x + threadIdx.x;   // float4 index
    float4 v = reinterpret_cast<const float4*>(x)[i];
    unsigned hw0 = (unsigned)__bfloat16_as_ushort(__float2bfloat16_rn(v.x))
                 | ((unsigned)__bfloat16_as_ushort(__float2bfloat16_rn(v.y)) << 16);
    unsigned hw1 = (unsigned)__bfloat16_as_ushort(__float2bfloat16_rn(v.z))
                 | ((unsigned)__bfloat16_as_ushort(__float2bfloat16_rn(v.w)) << 16);
    reinterpret_cast<uint2*>(g_xbf)[i] = make_uint2(hw0, hw1);
}

// ---------------------------------------------------------------------------
// fused bf16 HMMA filter GEMM + per-stripe top-4
// ---------------------------------------------------------------------------
extern __shared__ char smc[];

__device__ __forceinline__ void issue_chunk(uint32_t smem, int c, int tid, int nstart) {
    int t = c >> 1, h = c & 1;
    const char* base = (const char*)g_ebf
                     + (size_t)(nstart + t * NT) * 512 + h * 256;
    uint32_t dst = smem + SM_B + (uint32_t)(c & 3) * B_STAGE_B;
    #pragma unroll
    for (int j = 0; j < 4; j++) {
        int i = tid + j * THREADS;          // 0..2047
        int n = i >> 4, ch = i & 15;
        cpa16(dst + n * B_STRIDE_B + ch * 16, base + (size_t)n * 512 + ch * 16);
    }
}

__global__ void __launch_bounds__(THREADS, 1)
score_kernel() {
    const int tid = threadIdx.x;
    const int lane = tid & 31;
    const int warp = tid >> 5;
    const int mwarp = warp >> 2;            // 0..3 (32 rows each)
    const int nwarp = warp & 3;             // 0..3 (32 cols each)
    const int r0 = blockIdx.x * MT;
    const int nstart = blockIdx.y * STRIPE;
    const uint32_t smem = smem_u32(smc);

    // ---- prologue: A + hesq stripe, then 2 B chunks ----
    {
        const char* xh = (const char*)g_xbf + (size_t)r0 * 512;
        #pragma unroll
        for (int j = 0; j < 8; j++) {
            int i = tid + j * THREADS;      // 0..4095
            int row = i >> 5, ch = i & 31;
            cpa16(smem + SM_A + row * A_STRIDE_B + ch * 16, xh + (size_t)row * 512 + ch * 16);
        }
        for (int i = tid; i < 512; i += THREADS)
            cpa16(smem + SM_HESQ + i * 16, g_hesq + nstart + i * 4);
        CP_COMMIT();
        issue_chunk(smem, 0, tid, nstart); CP_COMMIT();
        issue_chunk(smem, 1, tid, nstart); CP_COMMIT();
    }

    float acc[2][4][4];                     // [m16 half][n8 block][frag]
    float tv[4][4];
    unsigned ti[4][4];
    #pragma unroll
    for (int r = 0; r < 4; r++)
        #pragma unroll
        for (int j = 0; j < 4; j++) { tv[r][j] = 3.4e38f; ti[r][j] = 0; }

    const uint32_t a_lane = (uint32_t)((lane & 15) * A_STRIDE_B + (lane >> 4) * 16);
    const uint32_t b_lane = (uint32_t)((lane & 15) * B_STRIDE_B + (lane >> 4) * 16);
    const uint32_t aBase = smem + SM_A + mwarp * 32 * A_STRIDE_B + a_lane;
    const float* hesq_s = (const float*)(smc + SM_HESQ);

    for (int c = 0; c < CHUNKS; c++) {
        if (c + 2 < CHUNKS) issue_chunk(smem, c + 2, tid, nstart);
        CP_COMMIT();
        CP_WAIT2();
        __syncthreads();

        const int h = c & 1;
        const uint32_t aCh = aBase + (uint32_t)h * 256;   // k offset of this chunk
        const uint32_t Bb = smem + SM_B + (uint32_t)(c & 3) * B_STAGE_B
                          + (uint32_t)(nwarp * 32) * B_STRIDE_B + b_lane;

        if (h == 0) {
            #pragma unroll
            for (int ms = 0; ms < 2; ms++)
                #pragma unroll
                for (int ns = 0; ns < 4; ns++)
                    #pragma unroll
                    for (int j = 0; j < 4; j++) acc[ms][ns][j] = 0.f;
        }

        // software-pipelined fragment double buffer over 8 k16 steps
        uint32_t bf[2][2][4], af[2][2][4];
        ldm4(bf[0][0], Bb);
        ldm4(bf[0][1], Bb + 16 * B_STRIDE_B);
        ldm4(af[0][0], aCh);
        ldm4(af[0][1], aCh + 16 * A_STRIDE_B);

        #pragma unroll
        for (int ks = 0; ks < 8; ks++) {
            const int cur = ks & 1, nxt = cur ^ 1;
            if (ks < 7) {
                const uint32_t ko = (ks + 1) * 32;
                ldm4(bf[nxt][0], Bb + ko);
                ldm4(bf[nxt][1], Bb + ko + 16 * B_STRIDE_B);
                ldm4(af[nxt][0], aCh + ko);
                ldm4(af[nxt][1], aCh + ko + 16 * A_STRIDE_B);
            }
            #pragma unroll
            for (int ns = 0; ns < 4; ns++) {
                uint32_t b0 = bf[cur][ns >> 1][ns & 1];
                uint32_t b1 = bf[cur][ns >> 1][(ns & 1) + 2];
                mma_bf16(acc[0][ns], af[cur][0], b0, b1);
                mma_bf16(acc[1][ns], af[cur][1], b0, b1);
            }
        }

        if (h == 1) {                        // tile done: score + top-4
            const int t = c >> 1;
            const int colbase = t * NT + nwarp * 32 + (lane & 3) * 2;
            #pragma unroll
            for (int ms = 0; ms < 2; ms++)
                #pragma unroll
                for (int ns = 0; ns < 4; ns++)
                    #pragma unroll
                    for (int i = 0; i < 4; i++) {
                        int col = colbase + ns * 8 + (i & 1);
                        float s = hesq_s[col] - acc[ms][ns][i];
                        const int rid = ms * 2 + (i >> 1);
                        if (s < tv[rid][3]) {
                            unsigned n = (unsigned)(nstart + col);
                            if (s < tv[rid][0]) {
                                tv[rid][3]=tv[rid][2]; ti[rid][3]=ti[rid][2];
                                tv[rid][2]=tv[rid][1]; ti[rid][2]=ti[rid][1];
                                tv[rid][1]=tv[rid][0]; ti[rid][1]=ti[rid][0];
                                tv[rid][0]=s; ti[rid][0]=n;
                            } else if (s < tv[rid][1]) {
                                tv[rid][3]=tv[rid][2]; ti[rid][3]=ti[rid][2];
                                tv[rid][2]=tv[rid][1]; ti[rid][2]=ti[rid][1];
                                tv[rid][1]=s; ti[rid][1]=n;
                            } else if (s < tv[rid][2]) {
                                tv[rid][3]=tv[rid][2]; ti[rid][3]=ti[rid][2];
                                tv[rid][2]=s; ti[rid][2]=n;
                            } else { tv[rid][3]=s; ti[rid][3]=n; }
                        }
                    }
        }
    }

    // ---- per-CTA merge: 16 partial top-4 lists per row -> stripe top-4 ----
    char* scr = smc + SM_MERGE;
    const int slot = nwarp * 4 + (lane & 3);
    #pragma unroll
    for (int rid = 0; rid < 4; rid++) {
        int row = mwarp * 32 + (rid >> 1) * 16 + (rid & 1) * 8 + (lane >> 2);
        char* p = scr + (row * 16 + slot) * 32;
        *reinterpret_cast<float4*>(p)      = make_float4(tv[rid][0], tv[rid][1], tv[rid][2], tv[rid][3]);
        *reinterpret_cast<uint4*>(p + 16)  = make_uint4(ti[rid][0], ti[rid][1], ti[rid][2], ti[rid][3]);
    }
    __syncthreads();

    if (tid < MT) {
        float v[4] = {3.4e38f, 3.4e38f, 3.4e38f, 3.4e38f};
        unsigned id[4] = {0, 0, 0, 0};
        const char* p = scr + tid * 16 * 32;
        for (int s = 0; s < 16; s++) {
            float4 pv = *reinterpret_cast<const float4*>(p + s * 32);
            uint4  pi = *reinterpret_cast<const uint4*>(p + s * 32 + 16);
            float cv[4] = {pv.x, pv.y, pv.z, pv.w};
            unsigned ci[4] = {pi.x, pi.y, pi.z, pi.w};
            #pragma unroll
            for (int j = 0; j < 4; j++) {
                float s1 = cv[j]; unsigned n1 = ci[j];
                if (s1 < v[3] || (s1 == v[3] && n1 < id[3])) {
                    if (s1 < v[0] || (s1 == v[0] && n1 < id[0])) {
                        v[3]=v[2];id[3]=id[2]; v[2]=v[1];id[2]=id[1]; v[1]=v[0];id[1]=id[0]; v[0]=s1;id[0]=n1;
                    } else if (s1 < v[1] || (s1 == v[1] && n1 < id[1])) {
                        v[3]=v[2];id[3]=id[2]; v[2]=v[1];id[2]=id[1]; v[1]=s1;id[1]=n1;
                    } else if (s1 < v[2] || (s1 == v[2] && n1 < id[2])) {
                        v[3]=v[2];id[3]=id[2]; v[2]=s1;id[2]=n1;
                    } else { v[3]=s1; id[3]=n1; }
                }
            }
        }
        g_pvals[blockIdx.y][r0 + tid] = make_float4(v[0], v[1], v[2], v[3]);
        g_pidx[blockIdx.y][r0 + tid]  = make_uint4(id[0], id[1], id[2], id[3]);
    }
}

// ---------------------------------------------------------------------------
// merge stripes + certify + exact candidate rescore
// ---------------------------------------------------------------------------
__global__ void merge_kernel(const float* __restrict__ x) {
    int r = blockIdx.x * blockDim.x + threadIdx.x;
    float v[4] = {3.4e38f, 3.4e38f, 3.4e38f, 3.4e38f};
    unsigned id[4] = {0, 0, 0, 0};
    float L = 3.4e38f;
    unsigned alli[16];
    #pragma unroll
    for (int s = 0; s < NSPLIT; s++) {
        float4 pv = g_pvals[s][r];
        uint4  pi = g_pidx[s][r];
        if (pv.w < L) L = pv.w;
        float cv[4] = {pv.x, pv.y, pv.z, pv.w};
        unsigned ci[4] = {pi.x, pi.y, pi.z, pi.w};
        #pragma unroll
        for (int j = 0; j < 4; j++) {
            alli[s * 4 + j] = ci[j];
            float s1 = cv[j]; unsigned n1 = ci[j];
            if (s1 < v[3] || (s1 == v[3] && n1 < id[3])) {
                if (s1 < v[0] || (s1 == v[0] && n1 < id[0])) {
                    v[3]=v[2];id[3]=id[2]; v[2]=v[1];id[2]=id[1]; v[1]=v[0];id[1]=id[0]; v[0]=s1;id[0]=n1;
                } else if (s1 < v[1] || (s1 == v[1] && n1 < id[1])) {
                    v[3]=v[2];id[3]=id[2]; v[2]=v[1];id[2]=id[1]; v[1]=s1;id[1]=n1;
                } else if (s1 < v[2] || (s1 == v[2] && n1 < id[2])) {
                    v[3]=v[2];id[3]=id[2]; v[2]=s1;id[2]=n1;
                } else { v[3]=s1; id[3]=n1; }
            }
        }
    }
    if (v[1] - v[0] >= TAU) { g_idx[r] = id[0]; return; }

    // exact fp32 rescore of all 16 candidates
    const float4* xv = reinterpret_cast<const float4*>(x + (size_t)r * K_DIM);
    float best = 3.4e38f; unsigned bi = 0xFFFFFFFFu;
    for (int j = 0; j < 16; j++) {
        unsigned n = alli[j];
        const float4* er = reinterpret_cast<const float4*>(g_embT + (size_t)n * K_DIM);
        float dot = 0.f;
        #pragma unroll 8
        for (int k = 0; k < K_DIM / 4; k++) {
            float4 a = xv[k], b = er[k];
            dot += a.x * b.x + a.y * b.y + a.z * b.z + a.w * b.w;
        }
        float s = g_hesq[n] - dot;
        if (s < best || (s == best && n < bi)) { best = s; bi = n; }
    }
    g_idx[r] = bi;
    if (L - v[0] < TAU) {              // candidate set not certified complete
        int p = atomicAdd(&g_nflag, 1);
        g_flag[p] = r;
    }
}

// ---------------------------------------------------------------------------
// full exact argmin for rare uncertified rows
// ---------------------------------------------------------------------------
__global__ void fixup_full_kernel(const float* __restrict__ x) {
    __shared__ float xs[K_DIM];
    __shared__ float wv[8];
    __shared__ unsigned wi[8];
    int nf = g_nflag;
    for (int f = blockIdx.x; f < nf; f += gridDim.x) {
        int r = g_flag[f];
        for (int k = threadIdx.x; k < K_DIM; k += blockDim.x) xs[k] = x[(size_t)r * K_DIM + k];
        __syncthreads();
        float best = 3.4e38f; unsigned bi = 0xFFFFFFFFu;
        for (int n = threadIdx.x; n < NCODES; n += blockDim.x) {
            const float4* er = reinterpret_cast<const float4*>(g_embT + (size_t)n * K_DIM);
            float dot = 0.f;
            #pragma unroll 8
            for (int k = 0; k < K_DIM / 4; k++) {
                float4 b = er[k];
                dot += xs[4*k] * b.x + xs[4*k+1] * b.y + xs[4*k+2] * b.z + xs[4*k+3] * b.w;
            }
            float s = g_hesq[n] - dot;
            if (s < best || (s == best && n < bi)) { best = s; bi = n; }
        }
        #pragma unroll
        for (int off = 16; off > 0; off >>= 1) {
            float ov = __shfl_down_sync(0xffffffffu, best, off);
            unsigned oi = __shfl_down_sync(0xffffffffu, bi, off);
            if (ov < best || (ov == best && oi < bi)) { best = ov; bi = oi; }
        }
        if ((threadIdx.x & 31) == 0) { wv[threadIdx.x >> 5] = best; wi[threadIdx.x >> 5] = bi; }
        __syncthreads();
        if (threadIdx.x == 0) {
            for (int w = 1; w < 8; w++)
                if (wv[w] < best || (wv[w] == best && wi[w] < bi)) { best = wv[w]; bi = wi[w]; }
            g_idx[r] = bi;
        }
        __syncthreads();
    }
}

// ---------------------------------------------------------------------------
__global__ void gather_kernel(float* __restrict__ out) {
    int r = blockIdx.x * 4 + (threadIdx.x >> 6);
    int c = threadIdx.x & 63;
    unsigned idx = g_idx[r] & (NCODES - 1);
    const float4* src = reinterpret_cast<const float4*>(g_embT + (size_t)idx * K_DIM);
    reinterpret_cast<float4*>(out + (size_t)r * K_DIM)[c] = src[c];
}

// ---------------------------------------------------------------------------
extern "C" void kernel_launch(void* const* d_in, const int* in_sizes, int n_in,
                              void* d_out, int out_size) {
    const float* x = (const float*)d_in[0];      // [32768, 256]
    const float* embed = (const float*)d_in[1];  // [256, 8192]
    float* out = (float*)d_out;

    cudaFuncSetAttribute(score_kernel, cudaFuncAttributeMaxDynamicSharedMemorySize,
                         SMEM_TOTAL);

    prep_kernel<<<NCODES / 256, 256>>>(embed);
    transpose_split_kernel<<<dim3(NCODES / 32, K_DIM / 32), dim3(32, 32)>>>(embed);
    xsplit_kernel<<<(M_TOTAL * K_DIM / 4) / 256, 256>>>(x);
    score_kernel<<<dim3(M_TOTAL / MT, NSPLIT), THREADS, SMEM_TOTAL>>>();
    merge_kernel<<<M_TOTAL / 256, 256>>>(x);
    fixup_full_kernel<<<32, 256>>>(x);
    gather_kernel<<<M_TOTAL / 4, 256>>>(out);
}